// round 15
// baseline (speedup 1.0000x reference)
#include <cuda_runtime.h>
#include <math.h>
#include <stdint.h>

#define BB 2
#define SQ 2048
#define SKV 4096
#define DM 1024
#define NH 16
#define DK 64
#define LOG2E 1.4426950408889634f

// ---------------- scratch (device globals; no allocation allowed) ----------------
__device__ float g_normed[(size_t)BB * SQ * DM];
__device__ float g_q[(size_t)BB * SQ * DM];
__device__ float g_k[(size_t)BB * SKV * DM];
__device__ float g_v[(size_t)BB * SKV * DM];
__device__ float g_ctx[(size_t)BB * SQ * DM];
__device__ float g_kvr[(size_t)BB * SKV * DM];
__device__ float g_wq[(size_t)DM * DM];
__device__ float g_wk[(size_t)DM * DM];
__device__ float g_wv[(size_t)DM * DM];
__device__ float g_wo[(size_t)DM * DM];

// ---------------- helpers ----------------
__device__ __forceinline__ uint32_t f2tf32(float x) {
    uint32_t u;
    asm("cvt.rna.tf32.f32 %0, %1;" : "=r"(u) : "f"(x));
    return u;
}
__device__ __forceinline__ float rtf(float x) { return __uint_as_float(f2tf32(x)); }

__device__ __forceinline__ void mma_tf32(float* c, const uint32_t* a, const uint32_t* b) {
    asm volatile(
        "mma.sync.aligned.m16n8k8.row.col.f32.tf32.tf32.f32 "
        "{%0,%1,%2,%3}, {%4,%5,%6,%7}, {%8,%9}, {%0,%1,%2,%3};"
        : "+f"(c[0]), "+f"(c[1]), "+f"(c[2]), "+f"(c[3])
        : "r"(a[0]), "r"(a[1]), "r"(a[2]), "r"(a[3]), "r"(b[0]), "r"(b[1]));
}

#define CP_ASYNC16(dst_u32, src_ptr) \
    asm volatile("cp.async.ca.shared.global [%0], [%1], 16;\n" :: "r"(dst_u32), "l"(src_ptr))
#define CP_COMMIT() asm volatile("cp.async.commit_group;\n" ::: "memory")

// ---------------- elementwise tf32 pre-round ----------------
__global__ void round_kernel(const float* __restrict__ in, float* __restrict__ out) {
    size_t i = ((size_t)blockIdx.x * 256 + threadIdx.x) * 4;
    float4 v = *(const float4*)(in + i);
    *(float4*)(out + i) = make_float4(rtf(v.x), rtf(v.y), rtf(v.z), rtf(v.w));
}

// ---------------- RMSNorm (output pre-rounded to tf32) ----------------
__global__ void rmsnorm_kernel(const float* __restrict__ x, const float* __restrict__ w) {
    int row = blockIdx.x;
    const float* xr = x + (size_t)row * DM;
    int i = threadIdx.x * 4;
    float4 xv = *(const float4*)(xr + i);
    float s = xv.x * xv.x + xv.y * xv.y + xv.z * xv.z + xv.w * xv.w;
#pragma unroll
    for (int off = 16; off > 0; off >>= 1) s += __shfl_xor_sync(0xffffffffu, s, off);
    __shared__ float red[8];
    int wid = threadIdx.x >> 5, lane = threadIdx.x & 31;
    if (lane == 0) red[wid] = s;
    __syncthreads();
    float tot = 0.f;
#pragma unroll
    for (int k = 0; k < 8; k++) tot += red[k];
    float inv = rsqrtf(tot * (1.0f / DM) + 1e-6f);
    float4 wv = *(const float4*)(w + i);
    *(float4*)&g_normed[(size_t)row * DM + i] =
        make_float4(rtf(wv.x * xv.x * inv), rtf(wv.y * xv.y * inv),
                    rtf(wv.z * xv.z * inv), rtf(wv.w * xv.w * inv));
}

// ---------------- tf32 GEMM: cp.async 3-stage pipeline, GBK=32 (fatter epochs) ----------------
#define GBK 32
#define LDKA 36
#define LDB 136
#define ASZ (128 * LDKA)            // 4608 words
#define BSZ (GBK * LDB)             // 4352 words
#define STAGE_W (ASZ + BSZ)
#define GEMM_SMEM_BYTES (3 * STAGE_W * 4)

template <bool RES, bool CVT>
__global__ __launch_bounds__(128) void tf32_gemm(const float* __restrict__ A,
                                                 const float* __restrict__ B,
                                                 const float* __restrict__ Res,
                                                 float* __restrict__ C,
                                                 int M, int N, int K) {
    extern __shared__ uint32_t smw[];
    int tid = threadIdx.x;
    int wid = tid >> 5, lane = tid & 31;
    int g = lane >> 2, tig = lane & 3;
    int warp_m = (wid >> 1) * 64, warp_n = (wid & 1) * 64;
    int m0 = blockIdx.y * 128, n0 = blockIdx.x * 128;

    uint32_t sbase = (uint32_t)__cvta_generic_to_shared(smw);
    const float* arow = A + (size_t)(m0 + tid) * K;

    float acc[4][8][4];
#pragma unroll
    for (int mt = 0; mt < 4; mt++)
#pragma unroll
        for (int nt = 0; nt < 8; nt++)
#pragma unroll
            for (int e = 0; e < 4; e++) acc[mt][nt][e] = 0.f;

    int nt_tiles = K / GBK;

#define ISSUE_STAGE(s, k0)                                                         \
    {                                                                              \
        uint32_t st = sbase + (uint32_t)(s) * (STAGE_W * 4);                       \
        const float* asrc = arow + (k0);                                           \
        _Pragma("unroll") for (int c = 0; c < 8; c++)                              \
            CP_ASYNC16(st + (tid * LDKA + c * 4) * 4, asrc + c * 4);               \
        _Pragma("unroll") for (int i = 0; i < 8; i++) {                            \
            int id = tid + 128 * i;                                                \
            int r = id >> 5, c4 = (id & 31) * 4;                                   \
            CP_ASYNC16(st + (ASZ + r * LDB + c4) * 4,                              \
                       B + (size_t)((k0) + r) * N + n0 + c4);                      \
        }                                                                          \
        CP_COMMIT();                                                               \
    }

    ISSUE_STAGE(0, 0);
    ISSUE_STAGE(1, GBK);

    for (int kt = 0; kt < nt_tiles; kt++) {
        int s = kt % 3;
        if (kt + 2 < nt_tiles) {
            asm volatile("cp.async.wait_group 1;\n" ::: "memory");
        } else {
            asm volatile("cp.async.wait_group 0;\n" ::: "memory");
        }
        __syncthreads();
        if (kt + 2 < nt_tiles) ISSUE_STAGE((kt + 2) % 3, (kt + 2) * GBK);

        const uint32_t* Ab = smw + s * STAGE_W;
        const uint32_t* Bb = Ab + ASZ;
#pragma unroll
        for (int ks = 0; ks < 4; ks++) {
            int kb = ks * 8;
            uint32_t af[4][4], bf[8][2];
#pragma unroll
            for (int mt = 0; mt < 4; mt++) {
                int mm = warp_m + mt * 16 + g;
                af[mt][0] = Ab[mm * LDKA + kb + tig];
                af[mt][1] = Ab[(mm + 8) * LDKA + kb + tig];
                af[mt][2] = Ab[mm * LDKA + kb + tig + 4];
                af[mt][3] = Ab[(mm + 8) * LDKA + kb + tig + 4];
            }
#pragma unroll
            for (int ntl = 0; ntl < 8; ntl++) {
                int nn = warp_n + ntl * 8 + g;
                bf[ntl][0] = Bb[(kb + tig) * LDB + nn];
                bf[ntl][1] = Bb[(kb + tig + 4) * LDB + nn];
            }
#pragma unroll
            for (int mt = 0; mt < 4; mt++)
#pragma unroll
                for (int ntl = 0; ntl < 8; ntl++) mma_tf32(acc[mt][ntl], af[mt], bf[ntl]);
        }
        __syncthreads();
    }

#pragma unroll
    for (int mt = 0; mt < 4; mt++) {
#pragma unroll
        for (int ntl = 0; ntl < 8; ntl++) {
            int row = m0 + warp_m + mt * 16 + g;
            int col = n0 + warp_n + ntl * 8 + 2 * tig;
            size_t i0 = (size_t)row * N + col;
            size_t i1 = (size_t)(row + 8) * N + col;
            float2 v0 = make_float2(acc[mt][ntl][0], acc[mt][ntl][1]);
            float2 v1 = make_float2(acc[mt][ntl][2], acc[mt][ntl][3]);
            if (RES) {
                float2 r0 = *(const float2*)&Res[i0];
                float2 r1 = *(const float2*)&Res[i1];
                v0.x += r0.x; v0.y += r0.y;
                v1.x += r1.x; v1.y += r1.y;
            }
            if (CVT) {
                v0.x = rtf(v0.x); v0.y = rtf(v0.y);
                v1.x = rtf(v1.x); v1.y = rtf(v1.y);
            }
            *(float2*)&C[i0] = v0;
            *(float2*)&C[i1] = v1;
        }
    }
}

// ---------------- Flash attention (R13 config — best measured) ----------------
#define TKV 64
#define NT (SKV / TKV)
#define ALDQ 260
#define KP_DBLK 516
#define VLD 72
#define SM_Q (64 * ALDQ)
#define SM_KP (8 * KP_DBLK)
#define SM_V (TKV * VLD)
#define ATTN_SMEM_U32 (SM_Q + 2 * SM_KP + 2 * SM_V)

__global__ __launch_bounds__(256, 1) void attn_tf32(const float* __restrict__ mask) {
    extern __shared__ uint32_t sm[];
    uint32_t* Qs = sm;
    uint32_t* KpB0 = sm + SM_Q;
    uint32_t* KpB1 = KpB0 + SM_KP;
    uint32_t* Vb0 = KpB1 + SM_KP;
    uint32_t* Vb1 = Vb0 + SM_V;

    int b = blockIdx.z, h = blockIdx.y;
    int q0 = blockIdx.x * 256;
    int tid = threadIdx.x;
    int lane = tid & 31;
    int wid = tid >> 5;
    int g = lane >> 2, tig = lane & 3;

    const float* mrow = mask + (size_t)b * SKV;

    {
        const float* qp = g_q + (size_t)(b * SQ + q0 + tid) * DM + h * DK;
#pragma unroll
        for (int i = 0; i < 16; i++) {
            float4 v = *(const float4*)(qp + i * 4);
            int d0 = i * 4;
            Qs[(d0 + 0) * ALDQ + tid] = f2tf32(v.x * LOG2E);
            Qs[(d0 + 1) * ALDQ + tid] = f2tf32(v.y * LOG2E);
            Qs[(d0 + 2) * ALDQ + tid] = f2tf32(v.z * LOG2E);
            Qs[(d0 + 3) * ALDQ + tid] = f2tf32(v.w * LOG2E);
        }
    }
    __syncthreads();

    uint32_t qreg[8][2][4];
#pragma unroll
    for (int ks = 0; ks < 8; ks++) {
        int kb = ks * 8;
#pragma unroll
        for (int mf = 0; mf < 2; mf++) {
            int mm = wid * 32 + mf * 16 + g;
            qreg[ks][mf][0] = Qs[(kb + tig) * ALDQ + mm];
            qreg[ks][mf][1] = Qs[(kb + tig) * ALDQ + mm + 8];
            qreg[ks][mf][2] = Qs[(kb + tig + 4) * ALDQ + mm];
            qreg[ks][mf][3] = Qs[(kb + tig + 4) * ALDQ + mm + 8];
        }
    }

    int dblk = tid & 7;
    int rgrp = tid >> 3;
    int vr = tid & 63;
    int vh = (tid >> 6) * 16;
    int vj = vr & 7;
    int vprow = (vr & ~7) | ((vj >> 1) + (vj & 1) * 4);
    const float* kbase = g_k + (size_t)(b * SKV) * DM + h * DK + dblk * 8;
    const float* vbase = g_v + (size_t)(b * SKV) * DM + h * DK + vh;

    uint32_t vdst0, vdst1;
    {
        uint32_t sbase = (uint32_t)__cvta_generic_to_shared(Vb0);
        vdst0 = sbase + (vprow * VLD + vh) * 4;
        vdst1 = vdst0 + SM_V * 4;
    }

    uint32_t kw[2][8];
    auto load_k = [&](int jt) {
#pragma unroll
        for (int i = 0; i < 2; i++) {
            const float* kp = kbase + (size_t)(jt * TKV + rgrp * 2 + i) * DM;
            float4 a = *(const float4*)kp;
            float4 c = *(const float4*)(kp + 4);
            kw[i][0] = __float_as_uint(a.x); kw[i][1] = __float_as_uint(a.y);
            kw[i][2] = __float_as_uint(a.z); kw[i][3] = __float_as_uint(a.w);
            kw[i][4] = __float_as_uint(c.x); kw[i][5] = __float_as_uint(c.y);
            kw[i][6] = __float_as_uint(c.z); kw[i][7] = __float_as_uint(c.w);
        }
    };
    auto store_k = [&](uint32_t* Kb) {
#pragma unroll
        for (int i = 0; i < 2; i++) {
            int r = rgrp * 2 + i;
            int x = (r & 3) * 2;
            uint32_t* outp = Kb + dblk * KP_DBLK + r * 8;
            uint32_t val[8];
#pragma unroll
            for (int p = 0; p < 8; p++) {
                int inner = p ^ x;
                val[p] = kw[i][(inner & 1) * 4 + (inner >> 1)];
            }
            *(uint4*)(outp) = make_uint4(val[0], val[1], val[2], val[3]);
            *(uint4*)(outp + 4) = make_uint4(val[4], val[5], val[6], val[7]);
        }
    };

    load_k(0);
    {
        const float* vp = vbase + (size_t)vr * DM;
#pragma unroll
        for (int i = 0; i < 4; i++) CP_ASYNC16(vdst0 + i * 16, vp + i * 4);
        CP_COMMIT();
    }
    store_k(KpB0);
    load_k(1);

    float ls[2][2];
    ls[0][0] = ls[0][1] = ls[1][0] = ls[1][1] = 0.f;
    float oacc[2][8][4];
#pragma unroll
    for (int mf = 0; mf < 2; mf++)
#pragma unroll
        for (int d = 0; d < 8; d++)
#pragma unroll
            for (int e = 0; e < 4; e++) oacc[mf][d][e] = 0.f;

    for (int jt = 0; jt < NT; jt++) {
        const uint32_t* Kc = (jt & 1) ? KpB1 : KpB0;
        const uint32_t* Vcur = (jt & 1) ? Vb1 : Vb0;

        asm volatile("cp.async.wait_group 0;\n" ::: "memory");
        __syncthreads();

        if (jt + 1 < NT) {
            uint32_t vdst = ((jt + 1) & 1) ? vdst1 : vdst0;
            const float* vnext = vbase + (size_t)((jt + 1) * TKV + vr) * DM;
#pragma unroll
            for (int i = 0; i < 4; i++) CP_ASYNC16(vdst + i * 16, vnext + i * 4);
            CP_COMMIT();
            store_k(((jt + 1) & 1) ? KpB1 : KpB0);
            if (jt + 2 < NT) load_k(jt + 2);
        }

        float sacc[2][8][4];
#pragma unroll
        for (int mf = 0; mf < 2; mf++)
#pragma unroll
            for (int n = 0; n < 8; n++)
#pragma unroll
                for (int e = 0; e < 4; e++) sacc[mf][n][e] = 0.f;
#pragma unroll
        for (int ks = 0; ks < 8; ks++) {
            const uint32_t* kpd = Kc + ks * KP_DBLK;
#pragma unroll
            for (int n = 0; n < 8; n++) {
                int kv = n * 8 + g;
                int p0 = (tig * 2) ^ ((kv & 3) * 2);
                uint2 pair = *(const uint2*)(kpd + kv * 8 + p0);
                uint32_t bf[2] = {pair.x, pair.y};
                mma_tf32(sacc[0][n], qreg[ks][0], bf);
                mma_tf32(sacc[1][n], qreg[ks][1], bf);
            }
        }

#pragma unroll
        for (int n = 0; n < 8; n++) {
            float2 mk = *(const float2*)&mrow[jt * TKV + n * 8 + 2 * tig];
#pragma unroll
            for (int mf = 0; mf < 2; mf++) {
                sacc[mf][n][0] = exp2f(fmaf(mk.x, LOG2E, sacc[mf][n][0]));
                sacc[mf][n][1] = exp2f(fmaf(mk.y, LOG2E, sacc[mf][n][1]));
                sacc[mf][n][2] = exp2f(fmaf(mk.x, LOG2E, sacc[mf][n][2]));
                sacc[mf][n][3] = exp2f(fmaf(mk.y, LOG2E, sacc[mf][n][3]));
            }
        }
#pragma unroll
        for (int mf = 0; mf < 2; mf++) {
            float rs0 = 0.f, rs1 = 0.f;
#pragma unroll
            for (int n = 0; n < 8; n++) {
                rs0 += sacc[mf][n][0] + sacc[mf][n][1];
                rs1 += sacc[mf][n][2] + sacc[mf][n][3];
            }
            ls[mf][0] += rs0;
            ls[mf][1] += rs1;
        }

#pragma unroll
        for (int ks = 0; ks < 8; ks++) {
            int kb = ks * 8;
            uint32_t pf0[4], pf1[4];
            pf0[0] = f2tf32(sacc[0][ks][0]);
            pf0[1] = f2tf32(sacc[0][ks][2]);
            pf0[2] = f2tf32(sacc[0][ks][1]);
            pf0[3] = f2tf32(sacc[0][ks][3]);
            pf1[0] = f2tf32(sacc[1][ks][0]);
            pf1[1] = f2tf32(sacc[1][ks][2]);
            pf1[2] = f2tf32(sacc[1][ks][1]);
            pf1[3] = f2tf32(sacc[1][ks][3]);
            const uint32_t* v0p = Vcur + (kb + tig) * VLD + g;
            const uint32_t* v1p = Vcur + (kb + tig + 4) * VLD + g;
#pragma unroll
            for (int n = 0; n < 8; n++) {
                uint32_t vf[2] = {v0p[n * 8], v1p[n * 8]};
                mma_tf32(oacc[0][n], pf0, vf);
                mma_tf32(oacc[1][n], pf1, vf);
            }
        }
    }

#pragma unroll
    for (int mf = 0; mf < 2; mf++) {
        float rs0 = ls[mf][0], rs1 = ls[mf][1];
        rs0 += __shfl_xor_sync(0xffffffffu, rs0, 1);
        rs0 += __shfl_xor_sync(0xffffffffu, rs0, 2);
        rs1 += __shfl_xor_sync(0xffffffffu, rs1, 1);
        rs1 += __shfl_xor_sync(0xffffffffu, rs1, 2);
        float inv0 = 1.0f / rs0, inv1 = 1.0f / rs1;
        int row0 = q0 + wid * 32 + mf * 16 + g;
        float* cp0 = g_ctx + (size_t)(b * SQ + row0) * DM + h * DK;
        float* cp1 = g_ctx + (size_t)(b * SQ + row0 + 8) * DM + h * DK;
#pragma unroll
        for (int n = 0; n < 8; n++) {
            int col = n * 8 + 2 * tig;
            *(float2*)&cp0[col] = make_float2(rtf(oacc[mf][n][0] * inv0), rtf(oacc[mf][n][1] * inv0));
            *(float2*)&cp1[col] = make_float2(rtf(oacc[mf][n][2] * inv1), rtf(oacc[mf][n][3] * inv1));
        }
    }
}

// ---------------- launch ----------------
extern "C" void kernel_launch(void* const* d_in, const int* in_sizes, int n_in,
                              void* d_out, int out_size) {
    const float* hidden = (const float*)d_in[0];
    const float* kv     = (const float*)d_in[1];
    const float* mask   = (const float*)d_in[2];
    const float* lnw    = (const float*)d_in[3];
    const float* Wq     = (const float*)d_in[4];
    const float* Wk     = (const float*)d_in[5];
    const float* Wv     = (const float*)d_in[6];
    const float* Wo     = (const float*)d_in[7];
    float* out = (float*)d_out;

    float *p_normed, *p_q, *p_k, *p_v, *p_ctx, *p_kvr, *p_wq, *p_wk, *p_wv, *p_wo;
    cudaGetSymbolAddress((void**)&p_normed, g_normed);
    cudaGetSymbolAddress((void**)&p_q, g_q);
    cudaGetSymbolAddress((void**)&p_k, g_k);
    cudaGetSymbolAddress((void**)&p_v, g_v);
    cudaGetSymbolAddress((void**)&p_ctx, g_ctx);
    cudaGetSymbolAddress((void**)&p_kvr, g_kvr);
    cudaGetSymbolAddress((void**)&p_wq, g_wq);
    cudaGetSymbolAddress((void**)&p_wk, g_wk);
    cudaGetSymbolAddress((void**)&p_wv, g_wv);
    cudaGetSymbolAddress((void**)&p_wo, g_wo);

    rmsnorm_kernel<<<BB * SQ, 256>>>(hidden, lnw);
    round_kernel<<<(BB * SKV * DM) / 1024, 256>>>(kv, p_kvr);
    round_kernel<<<(DM * DM) / 1024, 256>>>(Wq, p_wq);
    round_kernel<<<(DM * DM) / 1024, 256>>>(Wk, p_wk);
    round_kernel<<<(DM * DM) / 1024, 256>>>(Wv, p_wv);
    round_kernel<<<(DM * DM) / 1024, 256>>>(Wo, p_wo);

    cudaFuncSetAttribute(tf32_gemm<false, false>, cudaFuncAttributeMaxDynamicSharedMemorySize, GEMM_SMEM_BYTES);
    cudaFuncSetAttribute(tf32_gemm<false, true>, cudaFuncAttributeMaxDynamicSharedMemorySize, GEMM_SMEM_BYTES);
    cudaFuncSetAttribute(tf32_gemm<true, false>, cudaFuncAttributeMaxDynamicSharedMemorySize, GEMM_SMEM_BYTES);

    dim3 gq(DM / 128, (BB * SQ) / 128);
    dim3 gkv(DM / 128, (BB * SKV) / 128);
    tf32_gemm<false, false><<<gq, 128, GEMM_SMEM_BYTES>>>(p_normed, p_wq, nullptr, p_q, BB * SQ, DM, DM);
    tf32_gemm<false, true><<<gkv, 128, GEMM_SMEM_BYTES>>>(p_kvr, p_wk, nullptr, p_k, BB * SKV, DM, DM);
    tf32_gemm<false, true><<<gkv, 128, GEMM_SMEM_BYTES>>>(p_kvr, p_wv, nullptr, p_v, BB * SKV, DM, DM);

    const int ATTN_SMEM = ATTN_SMEM_U32 * 4;
    cudaFuncSetAttribute(attn_tf32, cudaFuncAttributeMaxDynamicSharedMemorySize, ATTN_SMEM);
    dim3 ga(SQ / 256, NH, BB);
    attn_tf32<<<ga, 256, ATTN_SMEM>>>(mask);

    tf32_gemm<true, false><<<gq, 128, GEMM_SMEM_BYTES>>>(p_ctx, p_wo, hidden, out, BB * SQ, DM, DM);
}

// round 16
// speedup vs baseline: 1.0581x; 1.0581x over previous
#include <cuda_runtime.h>
#include <math.h>
#include <stdint.h>

#define BB 2
#define SQ 2048
#define SKV 4096
#define DM 1024
#define NH 16
#define DK 64
#define LOG2E 1.4426950408889634f
#define NSPLIT 2
#define KVS (SKV / NSPLIT)

// ---------------- scratch (device globals; no allocation allowed) ----------------
__device__ float g_normed[(size_t)BB * SQ * DM];
__device__ float g_q[(size_t)BB * SQ * DM];
__device__ float g_k[(size_t)BB * SKV * DM];
__device__ float g_v[(size_t)BB * SKV * DM];
__device__ float g_ctx[(size_t)BB * SQ * DM];
__device__ float g_kvr[(size_t)BB * SKV * DM];
__device__ float g_wq[(size_t)DM * DM];
__device__ float g_wk[(size_t)DM * DM];
__device__ float g_wv[(size_t)DM * DM];
__device__ float g_wo[(size_t)DM * DM];
__device__ float g_part[(size_t)NSPLIT * BB * SQ * DM];      // unnormalized O partials
__device__ float g_lp[(size_t)NSPLIT * BB * SQ * NH];        // l partials

// ---------------- helpers ----------------
__device__ __forceinline__ uint32_t f2tf32(float x) {
    uint32_t u;
    asm("cvt.rna.tf32.f32 %0, %1;" : "=r"(u) : "f"(x));
    return u;
}
__device__ __forceinline__ float rtf(float x) { return __uint_as_float(f2tf32(x)); }

__device__ __forceinline__ void mma_tf32(float* c, const uint32_t* a, const uint32_t* b) {
    asm volatile(
        "mma.sync.aligned.m16n8k8.row.col.f32.tf32.tf32.f32 "
        "{%0,%1,%2,%3}, {%4,%5,%6,%7}, {%8,%9}, {%0,%1,%2,%3};"
        : "+f"(c[0]), "+f"(c[1]), "+f"(c[2]), "+f"(c[3])
        : "r"(a[0]), "r"(a[1]), "r"(a[2]), "r"(a[3]), "r"(b[0]), "r"(b[1]));
}

#define CP_ASYNC16(dst_u32, src_ptr) \
    asm volatile("cp.async.ca.shared.global [%0], [%1], 16;\n" :: "r"(dst_u32), "l"(src_ptr))
#define CP_COMMIT() asm volatile("cp.async.commit_group;\n" ::: "memory")

// ---------------- elementwise tf32 pre-round ----------------
__global__ void round_kernel(const float* __restrict__ in, float* __restrict__ out) {
    size_t i = ((size_t)blockIdx.x * 256 + threadIdx.x) * 4;
    float4 v = *(const float4*)(in + i);
    *(float4*)(out + i) = make_float4(rtf(v.x), rtf(v.y), rtf(v.z), rtf(v.w));
}

// 4 weight matrices in one launch (blockIdx.y selects)
__global__ void round_w4_kernel(const float* __restrict__ w0, const float* __restrict__ w1,
                                const float* __restrict__ w2, const float* __restrict__ w3,
                                float* __restrict__ o0, float* __restrict__ o1,
                                float* __restrict__ o2, float* __restrict__ o3) {
    const float* in = (blockIdx.y == 0) ? w0 : (blockIdx.y == 1) ? w1 : (blockIdx.y == 2) ? w2 : w3;
    float* out = (blockIdx.y == 0) ? o0 : (blockIdx.y == 1) ? o1 : (blockIdx.y == 2) ? o2 : o3;
    size_t i = ((size_t)blockIdx.x * 256 + threadIdx.x) * 4;
    float4 v = *(const float4*)(in + i);
    *(float4*)(out + i) = make_float4(rtf(v.x), rtf(v.y), rtf(v.z), rtf(v.w));
}

// ---------------- RMSNorm (output pre-rounded to tf32) ----------------
__global__ void rmsnorm_kernel(const float* __restrict__ x, const float* __restrict__ w) {
    int row = blockIdx.x;
    const float* xr = x + (size_t)row * DM;
    int i = threadIdx.x * 4;
    float4 xv = *(const float4*)(xr + i);
    float s = xv.x * xv.x + xv.y * xv.y + xv.z * xv.z + xv.w * xv.w;
#pragma unroll
    for (int off = 16; off > 0; off >>= 1) s += __shfl_xor_sync(0xffffffffu, s, off);
    __shared__ float red[8];
    int wid = threadIdx.x >> 5, lane = threadIdx.x & 31;
    if (lane == 0) red[wid] = s;
    __syncthreads();
    float tot = 0.f;
#pragma unroll
    for (int k = 0; k < 8; k++) tot += red[k];
    float inv = rsqrtf(tot * (1.0f / DM) + 1e-6f);
    float4 wv = *(const float4*)(w + i);
    *(float4*)&g_normed[(size_t)row * DM + i] =
        make_float4(rtf(wv.x * xv.x * inv), rtf(wv.y * xv.y * inv),
                    rtf(wv.z * xv.z * inv), rtf(wv.w * xv.w * inv));
}

// ---------------- tf32 GEMM: cp.async 3-stage pipeline, GBK=16 (R13 best) ----------------
#define GBK 16
#define LDKA 20
#define LDB 136
#define ASZ (128 * LDKA)
#define BSZ (GBK * LDB)
#define STAGE_W (ASZ + BSZ)
#define GEMM_SMEM_BYTES (3 * STAGE_W * 4)

#define ISSUE_STAGE(s, k0)                                                         \
    {                                                                              \
        uint32_t st = sbase + (uint32_t)(s) * (STAGE_W * 4);                       \
        const float* asrc = arow + (k0);                                           \
        _Pragma("unroll") for (int c = 0; c < 4; c++)                              \
            CP_ASYNC16(st + (tid * LDKA + c * 4) * 4, asrc + c * 4);               \
        _Pragma("unroll") for (int i = 0; i < 4; i++) {                            \
            int id = tid + 128 * i;                                                \
            int r = id >> 5, c4 = (id & 31) * 4;                                   \
            CP_ASYNC16(st + (ASZ + r * LDB + c4) * 4,                              \
                       B + (size_t)((k0) + r) * N + n0 + c4);                      \
        }                                                                          \
        CP_COMMIT();                                                               \
    }

#define GEMM_BODY(RES, CVT)                                                        \
    extern __shared__ uint32_t smw[];                                              \
    int tid = threadIdx.x;                                                         \
    int wid = tid >> 5, lane = tid & 31;                                           \
    int g = lane >> 2, tig = lane & 3;                                             \
    int warp_m = (wid >> 1) * 64, warp_n = (wid & 1) * 64;                         \
    int m0 = blockIdx.y * 128, n0 = blockIdx.x * 128;                              \
    uint32_t sbase = (uint32_t)__cvta_generic_to_shared(smw);                      \
    const float* arow = A + (size_t)(m0 + tid) * K;                                \
    float acc[4][8][4];                                                            \
    _Pragma("unroll") for (int mt = 0; mt < 4; mt++)                               \
        _Pragma("unroll") for (int nt = 0; nt < 8; nt++)                           \
            _Pragma("unroll") for (int e = 0; e < 4; e++) acc[mt][nt][e] = 0.f;    \
    int nt_tiles = K / GBK;                                                        \
    ISSUE_STAGE(0, 0);                                                             \
    ISSUE_STAGE(1, GBK);                                                           \
    for (int kt = 0; kt < nt_tiles; kt++) {                                        \
        int s = kt % 3;                                                            \
        if (kt + 2 < nt_tiles) {                                                   \
            asm volatile("cp.async.wait_group 1;\n" ::: "memory");                 \
        } else {                                                                   \
            asm volatile("cp.async.wait_group 0;\n" ::: "memory");                 \
        }                                                                          \
        __syncthreads();                                                           \
        if (kt + 2 < nt_tiles) ISSUE_STAGE((kt + 2) % 3, (kt + 2) * GBK);          \
        const uint32_t* Ab = smw + s * STAGE_W;                                    \
        const uint32_t* Bb = Ab + ASZ;                                             \
        _Pragma("unroll") for (int ks = 0; ks < 2; ks++) {                         \
            int kb = ks * 8;                                                       \
            uint32_t af[4][4], bf[8][2];                                           \
            _Pragma("unroll") for (int mt = 0; mt < 4; mt++) {                     \
                int mm = warp_m + mt * 16 + g;                                     \
                af[mt][0] = Ab[mm * LDKA + kb + tig];                              \
                af[mt][1] = Ab[(mm + 8) * LDKA + kb + tig];                        \
                af[mt][2] = Ab[mm * LDKA + kb + tig + 4];                          \
                af[mt][3] = Ab[(mm + 8) * LDKA + kb + tig + 4];                    \
            }                                                                      \
            _Pragma("unroll") for (int ntl = 0; ntl < 8; ntl++) {                  \
                int nn = warp_n + ntl * 8 + g;                                     \
                bf[ntl][0] = Bb[(kb + tig) * LDB + nn];                            \
                bf[ntl][1] = Bb[(kb + tig + 4) * LDB + nn];                        \
            }                                                                      \
            _Pragma("unroll") for (int mt = 0; mt < 4; mt++)                       \
                _Pragma("unroll") for (int ntl = 0; ntl < 8; ntl++)                \
                    mma_tf32(acc[mt][ntl], af[mt], bf[ntl]);                       \
        }                                                                          \
        __syncthreads();                                                           \
    }                                                                              \
    _Pragma("unroll") for (int mt = 0; mt < 4; mt++) {                             \
        _Pragma("unroll") for (int ntl = 0; ntl < 8; ntl++) {                      \
            int row = m0 + warp_m + mt * 16 + g;                                   \
            int col = n0 + warp_n + ntl * 8 + 2 * tig;                             \
            size_t i0 = (size_t)row * N + col;                                     \
            size_t i1 = (size_t)(row + 8) * N + col;                               \
            float2 v0 = make_float2(acc[mt][ntl][0], acc[mt][ntl][1]);             \
            float2 v1 = make_float2(acc[mt][ntl][2], acc[mt][ntl][3]);             \
            if (RES) {                                                             \
                float2 r0 = *(const float2*)&Res[i0];                              \
                float2 r1 = *(const float2*)&Res[i1];                              \
                v0.x += r0.x; v0.y += r0.y;                                        \
                v1.x += r1.x; v1.y += r1.y;                                        \
            }                                                                      \
            if (CVT) {                                                             \
                v0.x = rtf(v0.x); v0.y = rtf(v0.y);                                \
                v1.x = rtf(v1.x); v1.y = rtf(v1.y);                                \
            }                                                                      \
            *(float2*)&C[i0] = v0;                                                 \
            *(float2*)&C[i1] = v1;                                                 \
        }                                                                          \
    }

template <bool RES, bool CVT>
__global__ __launch_bounds__(128) void tf32_gemm(const float* __restrict__ A,
                                                 const float* __restrict__ B,
                                                 const float* __restrict__ Res,
                                                 float* __restrict__ C,
                                                 int M, int N, int K) {
    GEMM_BODY(RES, CVT)
}

// K and V projections fused in one launch (blockIdx.z selects B/C), CVT epilogue
__global__ __launch_bounds__(128) void tf32_gemm_kv(const float* __restrict__ A,
                                                    const float* __restrict__ B0,
                                                    const float* __restrict__ B1,
                                                    float* __restrict__ C0,
                                                    float* __restrict__ C1,
                                                    int M, int N, int K) {
    const float* B = blockIdx.z ? B1 : B0;
    float* C = blockIdx.z ? C1 : C0;
    const float* Res = nullptr;
    (void)Res;
    GEMM_BODY(false, true)
}

// ---------------- Flash attention v8: R13 config + split-KV (2 splits) ----------------
#define TKV 64
#define NTS (KVS / TKV)         // 32 iters per split
#define ALDQ 260
#define KP_DBLK 516
#define VLD 72
#define SM_Q (64 * ALDQ)
#define SM_KP (8 * KP_DBLK)
#define SM_V (TKV * VLD)
#define ATTN_SMEM_U32 (SM_Q + 2 * SM_KP + 2 * SM_V)

__global__ __launch_bounds__(256, 1) void attn_tf32(const float* __restrict__ mask) {
    extern __shared__ uint32_t sm[];
    uint32_t* Qs = sm;
    uint32_t* KpB0 = sm + SM_Q;
    uint32_t* KpB1 = KpB0 + SM_KP;
    uint32_t* Vb0 = KpB1 + SM_KP;
    uint32_t* Vb1 = Vb0 + SM_V;

    int b = blockIdx.z >> 1, split = blockIdx.z & 1;
    int h = blockIdx.y;
    int q0 = blockIdx.x * 256;
    int kv0 = split * KVS;
    int tid = threadIdx.x;
    int lane = tid & 31;
    int wid = tid >> 5;
    int g = lane >> 2, tig = lane & 3;

    const float* mrow = mask + (size_t)b * SKV + kv0;

    {
        const float* qp = g_q + (size_t)(b * SQ + q0 + tid) * DM + h * DK;
#pragma unroll
        for (int i = 0; i < 16; i++) {
            float4 v = *(const float4*)(qp + i * 4);
            int d0 = i * 4;
            Qs[(d0 + 0) * ALDQ + tid] = f2tf32(v.x * LOG2E);
            Qs[(d0 + 1) * ALDQ + tid] = f2tf32(v.y * LOG2E);
            Qs[(d0 + 2) * ALDQ + tid] = f2tf32(v.z * LOG2E);
            Qs[(d0 + 3) * ALDQ + tid] = f2tf32(v.w * LOG2E);
        }
    }
    __syncthreads();

    uint32_t qreg[8][2][4];
#pragma unroll
    for (int ks = 0; ks < 8; ks++) {
        int kb = ks * 8;
#pragma unroll
        for (int mf = 0; mf < 2; mf++) {
            int mm = wid * 32 + mf * 16 + g;
            qreg[ks][mf][0] = Qs[(kb + tig) * ALDQ + mm];
            qreg[ks][mf][1] = Qs[(kb + tig) * ALDQ + mm + 8];
            qreg[ks][mf][2] = Qs[(kb + tig + 4) * ALDQ + mm];
            qreg[ks][mf][3] = Qs[(kb + tig + 4) * ALDQ + mm + 8];
        }
    }

    int dblk = tid & 7;
    int rgrp = tid >> 3;
    int vr = tid & 63;
    int vh = (tid >> 6) * 16;
    int vj = vr & 7;
    int vprow = (vr & ~7) | ((vj >> 1) + (vj & 1) * 4);
    const float* kbase = g_k + (size_t)(b * SKV + kv0) * DM + h * DK + dblk * 8;
    const float* vbase = g_v + (size_t)(b * SKV + kv0) * DM + h * DK + vh;

    uint32_t vdst0, vdst1;
    {
        uint32_t sbase = (uint32_t)__cvta_generic_to_shared(Vb0);
        vdst0 = sbase + (vprow * VLD + vh) * 4;
        vdst1 = vdst0 + SM_V * 4;
    }

    uint32_t kw[2][8];
    auto load_k = [&](int jt) {
#pragma unroll
        for (int i = 0; i < 2; i++) {
            const float* kp = kbase + (size_t)(jt * TKV + rgrp * 2 + i) * DM;
            float4 a = *(const float4*)kp;
            float4 c = *(const float4*)(kp + 4);
            kw[i][0] = __float_as_uint(a.x); kw[i][1] = __float_as_uint(a.y);
            kw[i][2] = __float_as_uint(a.z); kw[i][3] = __float_as_uint(a.w);
            kw[i][4] = __float_as_uint(c.x); kw[i][5] = __float_as_uint(c.y);
            kw[i][6] = __float_as_uint(c.z); kw[i][7] = __float_as_uint(c.w);
        }
    };
    auto store_k = [&](uint32_t* Kb) {
#pragma unroll
        for (int i = 0; i < 2; i++) {
            int r = rgrp * 2 + i;
            int x = (r & 3) * 2;
            uint32_t* outp = Kb + dblk * KP_DBLK + r * 8;
            uint32_t val[8];
#pragma unroll
            for (int p = 0; p < 8; p++) {
                int inner = p ^ x;
                val[p] = kw[i][(inner & 1) * 4 + (inner >> 1)];
            }
            *(uint4*)(outp) = make_uint4(val[0], val[1], val[2], val[3]);
            *(uint4*)(outp + 4) = make_uint4(val[4], val[5], val[6], val[7]);
        }
    };

    load_k(0);
    {
        const float* vp = vbase + (size_t)vr * DM;
#pragma unroll
        for (int i = 0; i < 4; i++) CP_ASYNC16(vdst0 + i * 16, vp + i * 4);
        CP_COMMIT();
    }
    store_k(KpB0);
    load_k(1);

    float ls[2][2];
    ls[0][0] = ls[0][1] = ls[1][0] = ls[1][1] = 0.f;
    float oacc[2][8][4];
#pragma unroll
    for (int mf = 0; mf < 2; mf++)
#pragma unroll
        for (int d = 0; d < 8; d++)
#pragma unroll
            for (int e = 0; e < 4; e++) oacc[mf][d][e] = 0.f;

    for (int jt = 0; jt < NTS; jt++) {
        const uint32_t* Kc = (jt & 1) ? KpB1 : KpB0;
        const uint32_t* Vcur = (jt & 1) ? Vb1 : Vb0;

        asm volatile("cp.async.wait_group 0;\n" ::: "memory");
        __syncthreads();

        if (jt + 1 < NTS) {
            uint32_t vdst = ((jt + 1) & 1) ? vdst1 : vdst0;
            const float* vnext = vbase + (size_t)((jt + 1) * TKV + vr) * DM;
#pragma unroll
            for (int i = 0; i < 4; i++) CP_ASYNC16(vdst + i * 16, vnext + i * 4);
            CP_COMMIT();
            store_k(((jt + 1) & 1) ? KpB1 : KpB0);
            if (jt + 2 < NTS) load_k(jt + 2);
        }

        float sacc[2][8][4];
#pragma unroll
        for (int mf = 0; mf < 2; mf++)
#pragma unroll
            for (int n = 0; n < 8; n++)
#pragma unroll
                for (int e = 0; e < 4; e++) sacc[mf][n][e] = 0.f;
#pragma unroll
        for (int ks = 0; ks < 8; ks++) {
            const uint32_t* kpd = Kc + ks * KP_DBLK;
#pragma unroll
            for (int n = 0; n < 8; n++) {
                int kv = n * 8 + g;
                int p0 = (tig * 2) ^ ((kv & 3) * 2);
                uint2 pair = *(const uint2*)(kpd + kv * 8 + p0);
                uint32_t bf[2] = {pair.x, pair.y};
                mma_tf32(sacc[0][n], qreg[ks][0], bf);
                mma_tf32(sacc[1][n], qreg[ks][1], bf);
            }
        }

#pragma unroll
        for (int n = 0; n < 8; n++) {
            float2 mk = *(const float2*)&mrow[jt * TKV + n * 8 + 2 * tig];
#pragma unroll
            for (int mf = 0; mf < 2; mf++) {
                sacc[mf][n][0] = exp2f(fmaf(mk.x, LOG2E, sacc[mf][n][0]));
                sacc[mf][n][1] = exp2f(fmaf(mk.y, LOG2E, sacc[mf][n][1]));
                sacc[mf][n][2] = exp2f(fmaf(mk.x, LOG2E, sacc[mf][n][2]));
                sacc[mf][n][3] = exp2f(fmaf(mk.y, LOG2E, sacc[mf][n][3]));
            }
        }
#pragma unroll
        for (int mf = 0; mf < 2; mf++) {
            float rs0 = 0.f, rs1 = 0.f;
#pragma unroll
            for (int n = 0; n < 8; n++) {
                rs0 += sacc[mf][n][0] + sacc[mf][n][1];
                rs1 += sacc[mf][n][2] + sacc[mf][n][3];
            }
            ls[mf][0] += rs0;
            ls[mf][1] += rs1;
        }

#pragma unroll
        for (int ks = 0; ks < 8; ks++) {
            int kb = ks * 8;
            uint32_t pf0[4], pf1[4];
            pf0[0] = f2tf32(sacc[0][ks][0]);
            pf0[1] = f2tf32(sacc[0][ks][2]);
            pf0[2] = f2tf32(sacc[0][ks][1]);
            pf0[3] = f2tf32(sacc[0][ks][3]);
            pf1[0] = f2tf32(sacc[1][ks][0]);
            pf1[1] = f2tf32(sacc[1][ks][2]);
            pf1[2] = f2tf32(sacc[1][ks][1]);
            pf1[3] = f2tf32(sacc[1][ks][3]);
            const uint32_t* v0p = Vcur + (kb + tig) * VLD + g;
            const uint32_t* v1p = Vcur + (kb + tig + 4) * VLD + g;
#pragma unroll
            for (int n = 0; n < 8; n++) {
                uint32_t vf[2] = {v0p[n * 8], v1p[n * 8]};
                mma_tf32(oacc[0][n], pf0, vf);
                mma_tf32(oacc[1][n], pf1, vf);
            }
        }
    }

    // epilogue: write UNNORMALIZED partial O and partial l
    size_t pbase = (size_t)split * BB * SQ;
#pragma unroll
    for (int mf = 0; mf < 2; mf++) {
        float rs0 = ls[mf][0], rs1 = ls[mf][1];
        rs0 += __shfl_xor_sync(0xffffffffu, rs0, 1);
        rs0 += __shfl_xor_sync(0xffffffffu, rs0, 2);
        rs1 += __shfl_xor_sync(0xffffffffu, rs1, 1);
        rs1 += __shfl_xor_sync(0xffffffffu, rs1, 2);
        int row0 = q0 + wid * 32 + mf * 16 + g;
        if (tig == 0) {
            g_lp[(pbase + b * SQ + row0) * NH + h] = rs0;
            g_lp[(pbase + b * SQ + row0 + 8) * NH + h] = rs1;
        }
        float* cp0 = g_part + (pbase + b * SQ + row0) * DM + h * DK;
        float* cp1 = g_part + (pbase + b * SQ + row0 + 8) * DM + h * DK;
#pragma unroll
        for (int n = 0; n < 8; n++) {
            int col = n * 8 + 2 * tig;
            *(float2*)&cp0[col] = make_float2(oacc[mf][n][0], oacc[mf][n][1]);
            *(float2*)&cp1[col] = make_float2(oacc[mf][n][2], oacc[mf][n][3]);
        }
    }
}

// ---------------- combine split-KV partials -> normalized tf32 ctx ----------------
__global__ void combine_kernel() {
    size_t gid = (size_t)blockIdx.x * 256 + threadIdx.x;   // one float4 each
    size_t row = gid >> 8;                                  // 256 float4 per row
    int c4 = (int)(gid & 255) * 4;
    int hh = c4 >> 6;
    float l = g_lp[row * NH + hh] + g_lp[(size_t)BB * SQ * NH + row * NH + hh];
    float inv = 1.0f / l;
    size_t idx = row * DM + c4;
    float4 a = *(const float4*)&g_part[idx];
    float4 c = *(const float4*)&g_part[(size_t)BB * SQ * DM + idx];
    *(float4*)&g_ctx[idx] = make_float4(rtf((a.x + c.x) * inv), rtf((a.y + c.y) * inv),
                                        rtf((a.z + c.z) * inv), rtf((a.w + c.w) * inv));
}

// ---------------- launch ----------------
extern "C" void kernel_launch(void* const* d_in, const int* in_sizes, int n_in,
                              void* d_out, int out_size) {
    const float* hidden = (const float*)d_in[0];
    const float* kv     = (const float*)d_in[1];
    const float* mask   = (const float*)d_in[2];
    const float* lnw    = (const float*)d_in[3];
    const float* Wq     = (const float*)d_in[4];
    const float* Wk     = (const float*)d_in[5];
    const float* Wv     = (const float*)d_in[6];
    const float* Wo     = (const float*)d_in[7];
    float* out = (float*)d_out;

    float *p_normed, *p_q, *p_k, *p_v, *p_ctx, *p_kvr, *p_wq, *p_wk, *p_wv, *p_wo;
    cudaGetSymbolAddress((void**)&p_normed, g_normed);
    cudaGetSymbolAddress((void**)&p_q, g_q);
    cudaGetSymbolAddress((void**)&p_k, g_k);
    cudaGetSymbolAddress((void**)&p_v, g_v);
    cudaGetSymbolAddress((void**)&p_ctx, g_ctx);
    cudaGetSymbolAddress((void**)&p_kvr, g_kvr);
    cudaGetSymbolAddress((void**)&p_wq, g_wq);
    cudaGetSymbolAddress((void**)&p_wk, g_wk);
    cudaGetSymbolAddress((void**)&p_wv, g_wv);
    cudaGetSymbolAddress((void**)&p_wo, g_wo);

    rmsnorm_kernel<<<BB * SQ, 256>>>(hidden, lnw);
    round_kernel<<<(BB * SKV * DM) / 1024, 256>>>(kv, p_kvr);
    dim3 gw((DM * DM) / 1024, 4);
    round_w4_kernel<<<gw, 256>>>(Wq, Wk, Wv, Wo, p_wq, p_wk, p_wv, p_wo);

    cudaFuncSetAttribute(tf32_gemm<false, false>, cudaFuncAttributeMaxDynamicSharedMemorySize, GEMM_SMEM_BYTES);
    cudaFuncSetAttribute(tf32_gemm_kv, cudaFuncAttributeMaxDynamicSharedMemorySize, GEMM_SMEM_BYTES);
    cudaFuncSetAttribute(tf32_gemm<true, false>, cudaFuncAttributeMaxDynamicSharedMemorySize, GEMM_SMEM_BYTES);

    dim3 gq(DM / 128, (BB * SQ) / 128);
    dim3 gkv2(DM / 128, (BB * SKV) / 128, 2);
    tf32_gemm<false, false><<<gq, 128, GEMM_SMEM_BYTES>>>(p_normed, p_wq, nullptr, p_q, BB * SQ, DM, DM);
    tf32_gemm_kv<<<gkv2, 128, GEMM_SMEM_BYTES>>>(p_kvr, p_wk, p_wv, p_k, p_v, BB * SKV, DM, DM);

    const int ATTN_SMEM = ATTN_SMEM_U32 * 4;
    cudaFuncSetAttribute(attn_tf32, cudaFuncAttributeMaxDynamicSharedMemorySize, ATTN_SMEM);
    dim3 ga(SQ / 256, NH, BB * NSPLIT);
    attn_tf32<<<ga, 256, ATTN_SMEM>>>(mask);

    combine_kernel<<<(BB * SQ * DM) / 1024, 256>>>();

    tf32_gemm<true, false><<<gq, 128, GEMM_SMEM_BYTES>>>(p_ctx, p_wo, hidden, out, BB * SQ, DM, DM);
}